// round 16
// baseline (speedup 1.0000x reference)
#include <cuda_runtime.h>
#include <cuda_bf16.h>
#include <cstdint>

// ---------------- problem constants ----------------
#define CLASSES   100000
#define CPAD      100096               // 782*128 padded classes
#define KDIM      512
#define BATCHN    512
#define NCTA      782                  // class tiles of 128
#define PPAD      784                  // padded partial stride per batch row
#define NCHUNK    8                    // K chunks of 64
#define NSLICE    4
#define EXPK      92.33248261689366f   // 64 * log2(e)

static constexpr float C_COS_M = 0.8775825618903728f;   // cos(0.5)
static constexpr float C_SIN_M = 0.479425538604203f;    // sin(0.5)
static constexpr float C_TH    = -0.8775825618903728f;  // cos(pi-0.5)
static constexpr float C_MM    = 0.23971276930210156f;  // sin(pi-0.5)*0.5

static const int SLICE_OFF[NSLICE + 1] = {0, 196, 392, 588, 782};  // ctile bounds

// ---------------- device scratch (static: no allocations allowed) ----------------
__device__ __nv_bfloat16 g_xn[BATCHN * KDIM];          // normalized x, bf16
__device__ __nv_bfloat16 g_wb[(size_t)CPAD * KDIM];    // normalized w, bf16 (zero-padded)
__device__ float g_partials[(size_t)BATCHN * PPAD];    // per (b, class-tile) exp sums
__device__ float g_cost[BATCHN];                       // cosine at target class
__device__ float g_lossb[BATCHN];                      // per-sample loss
__device__ int   g_tgt[BATCHN];                        // targets as int32 (dtype-robust)
__device__ unsigned g_ctr;                             // last-block-done counter

// ---------------- helpers ----------------
__device__ __forceinline__ uint32_t smem_u32(const void* p) {
    uint32_t a;
    asm("{ .reg .u64 t; cvta.to.shared.u64 t, %1; cvt.u32.u64 %0, t; }" : "=r"(a) : "l"(p));
    return a;
}
__device__ __forceinline__ void cp_async16_cg(uint32_t saddr, const void* gptr) {
    asm volatile("cp.async.cg.shared.global [%0], [%1], 16;"
                 :: "r"(saddr), "l"(__cvta_generic_to_global(gptr)));
}
__device__ __forceinline__ void cp_async16_ca(uint32_t saddr, const void* gptr) {
    asm volatile("cp.async.ca.shared.global [%0], [%1], 16;"
                 :: "r"(saddr), "l"(__cvta_generic_to_global(gptr)));
}
__device__ __forceinline__ void cp_commit() {
    asm volatile("cp.async.commit_group;" ::: "memory");
}
template <int N>
__device__ __forceinline__ void cp_wait() {
    asm volatile("cp.async.wait_group %0;" :: "n"(N) : "memory");
}
__device__ __forceinline__ void ldsm_x4(uint32_t* r, uint32_t addr) {
    asm volatile("ldmatrix.sync.aligned.m8n8.x4.shared.b16 {%0,%1,%2,%3}, [%4];"
                 : "=r"(r[0]), "=r"(r[1]), "=r"(r[2]), "=r"(r[3]) : "r"(addr));
}
__device__ __forceinline__ void mma_bf16(float* d, const uint32_t* a, uint32_t b0, uint32_t b1) {
    asm volatile(
        "mma.sync.aligned.m16n8k16.row.col.f32.bf16.bf16.f32 "
        "{%0,%1,%2,%3}, {%4,%5,%6,%7}, {%8,%9}, {%0,%1,%2,%3};"
        : "+f"(d[0]), "+f"(d[1]), "+f"(d[2]), "+f"(d[3])
        : "r"(a[0]), "r"(a[1]), "r"(a[2]), "r"(a[3]), "r"(b0), "r"(b1));
}
__device__ __forceinline__ uint32_t pack_bf16x2(float a, float b) {
    __nv_bfloat162 p = __floats2bfloat162_rn(a, b);
    return *(uint32_t*)&p;
}
__device__ __forceinline__ float ex2_approx(float x) {   // bare MUFU.EX2
    float r;
    asm("ex2.approx.f32 %0, %1;" : "=f"(r) : "f"(x));
    return r;
}

// ---------------- dynamic smem layout for GEMM (3-stage) ----------------
#define SM_STAGE  32768
#define SM_RSUM   98304     // 128*2 f32 = 1024
#define SM_TGT    99328     // 128 int = 512
#define SMEM_DYN  (99840 + 1024)

// ======================= K1: normalize x -> bf16 (+ target prep + ctr reset) ===========
__global__ void __launch_bounds__(128) k_norm_x(const float* __restrict__ x,
                                                const int* __restrict__ t32) {
    __shared__ float red[4];
    __shared__ int nz;
    int b = blockIdx.x;
    int tid = threadIdx.x;

    int tv[4];
    if (b == 0) {
        if (tid == 0) { nz = 0; g_ctr = 0u; }
        #pragma unroll
        for (int i = 0; i < 4; i++) tv[i] = t32[tid + i * 128];
    }

    float4 v = *(const float4*)(x + (size_t)b * KDIM + tid * 4);
    float sq = v.x * v.x + v.y * v.y + v.z * v.z + v.w * v.w;
    #pragma unroll
    for (int m = 16; m >= 1; m >>= 1) sq += __shfl_xor_sync(0xffffffffu, sq, m);
    if ((tid & 31) == 0) red[tid >> 5] = sq;
    __syncthreads();

    if (b == 0) {
        #pragma unroll
        for (int i = 0; i < 4; i++) {
            int idx = tid + i * 128;
            if ((idx & 1) && tv[i] != 0) atomicAdd(&nz, 1);
        }
    }
    __syncthreads();

    float inv = 1.0f / fmaxf(sqrtf(red[0] + red[1] + red[2] + red[3]), 1e-12f);
    uint2 pk;
    pk.x = pack_bf16x2(v.x * inv, v.y * inv);
    pk.y = pack_bf16x2(v.z * inv, v.w * inv);
    *(uint2*)(&g_xn[(size_t)b * KDIM + tid * 4]) = pk;

    if (b == 0) {
        bool is64 = (nz == 0);
        #pragma unroll
        for (int i = 0; i < 4; i++) {
            int idx = tid + i * 128;
            g_tgt[idx] = is64 ? t32[2 * idx] : t32[idx];
        }
    }
}

// ======================= K0: normalize weight slice -> bf16 (warp per row) =============
__global__ void __launch_bounds__(128) k_norm_w(const float* __restrict__ w, int row0) {
    int row = row0 + blockIdx.x * 4 + (threadIdx.x >> 5);
    int lane = threadIdx.x & 31;
    if (row >= CLASSES) {
        #pragma unroll
        for (int i = 0; i < 4; i++)
            *(uint2*)(&g_wb[(size_t)row * KDIM + i * 128 + lane * 4]) = make_uint2(0u, 0u);
        return;
    }
    float4 v[4];
    float sq = 0.0f;
    #pragma unroll
    for (int i = 0; i < 4; i++) {
        v[i] = *(const float4*)(w + (size_t)row * KDIM + i * 128 + lane * 4);
        sq += v[i].x * v[i].x + v[i].y * v[i].y + v[i].z * v[i].z + v[i].w * v[i].w;
    }
    #pragma unroll
    for (int m = 16; m >= 1; m >>= 1) sq += __shfl_xor_sync(0xffffffffu, sq, m);
    float inv = 1.0f / fmaxf(sqrtf(sq), 1e-12f);
    #pragma unroll
    for (int i = 0; i < 4; i++) {
        uint2 pk;
        pk.x = pack_bf16x2(v[i].x * inv, v[i].y * inv);
        pk.y = pack_bf16x2(v[i].z * inv, v[i].w * inv);
        *(uint2*)(&g_wb[(size_t)row * KDIM + i * 128 + lane * 4]) = pk;
    }
}

// ======================= K2: HMMA GEMM + partial LSE (ctile-offset slice) ==============
__global__ void __launch_bounds__(256, 2) k_gemm(int ct0) {
    extern __shared__ char dsm[];
    uint32_t base = smem_u32(dsm);
    uint32_t A = (base + 1023u) & ~1023u;
    char* SA = dsm + (A - base);

    int tid = threadIdx.x;
    int wid = tid >> 5;
    int lid = tid & 31;
    int warpM = wid >> 1;          // 0..3  (32 batch rows each)
    int warpN = wid & 1;           // 0..1  (64 class cols each)

    int ctile = ct0 + (blockIdx.x >> 2);
    int btile = blockIdx.x & 3;
    int cls0 = ctile * 128;
    int b0 = btile * 128;

    int lrow = tid >> 3;                   // 0..31
    int lcol = (tid & 7) * 16;
    uint32_t st_sw = A + (uint32_t)(lrow * 128 + (lcol ^ ((lrow & 7) << 4)));
    const char* pA = (const char*)g_xn + (size_t)b0 * 1024 + lrow * 1024 + (tid & 7) * 16;
    const char* pB = (const char*)g_wb + (size_t)cls0 * 1024 + lrow * 1024 + (tid & 7) * 16;

    auto ld = [&](int kc, int st) {
        #pragma unroll
        for (int i = 0; i < 4; i++)
            cp_async16_ca(st_sw + st * SM_STAGE + i * 4096, pA + i * 32768 + kc * 128);
        #pragma unroll
        for (int i = 0; i < 4; i++)
            cp_async16_cg(st_sw + st * SM_STAGE + 16384 + i * 4096, pB + i * 32768 + kc * 128);
        cp_commit();
    };

    int lr = lid & 15;
    int lh = (lid >> 4) * 16;
    uint32_t pat = (uint32_t)((lr & 7) << 4);
    uint32_t ko[4];
    #pragma unroll
    for (int ks = 0; ks < 4; ks++) ko[ks] = (uint32_t)((ks * 32 + lh) ^ pat);
    uint32_t ldA = A + (uint32_t)((warpM * 32 + lr) * 128);
    uint32_t ldB = A + 16384u + (uint32_t)((warpN * 64 + lr) * 128);

    float acc[2][8][4];
    #pragma unroll
    for (int i = 0; i < 2; i++)
        #pragma unroll
        for (int j = 0; j < 8; j++)
            #pragma unroll
            for (int q = 0; q < 4; q++) acc[i][j][q] = 0.0f;

    int* tgt_s = (int*)(SA + SM_TGT);
    if (tid < 128) tgt_s[tid] = g_tgt[b0 + tid];

    ld(0, 0);
    ld(1, 1);

    uint32_t bfr[2][4][4];
    uint32_t afr[2][2][4];

    #pragma unroll
    for (int kc = 0; kc < NCHUNK; kc++) {
        if (kc < NCHUNK - 1) cp_wait<1>();
        else                 cp_wait<0>();
        __syncthreads();      // stage kc visible; stage (kc+2)%3 reusable

        if (kc + 2 < NCHUNK) ld(kc + 2, (kc + 2) % 3);

        const uint32_t sOff = (uint32_t)((kc % 3) * SM_STAGE);

        #pragma unroll
        for (int nt4 = 0; nt4 < 4; nt4++)
            ldsm_x4(bfr[0][nt4], ldB + sOff + nt4 * 2048 + ko[0]);
        #pragma unroll
        for (int mt = 0; mt < 2; mt++)
            ldsm_x4(afr[0][mt], ldA + sOff + mt * 2048 + ko[0]);

        #pragma unroll
        for (int ks = 0; ks < 4; ks++) {
            int cur = ks & 1;
            int nxt = cur ^ 1;
            if (ks < 3) {
                #pragma unroll
                for (int nt4 = 0; nt4 < 4; nt4++)
                    ldsm_x4(bfr[nxt][nt4], ldB + sOff + nt4 * 2048 + ko[ks + 1]);
                #pragma unroll
                for (int mt = 0; mt < 2; mt++)
                    ldsm_x4(afr[nxt][mt], ldA + sOff + mt * 2048 + ko[ks + 1]);
            }
            #pragma unroll
            for (int mt = 0; mt < 2; mt++) {
                #pragma unroll
                for (int nt4 = 0; nt4 < 4; nt4++) {
                    mma_bf16(acc[mt][nt4 * 2 + 0], afr[cur][mt], bfr[cur][nt4][0], bfr[cur][nt4][2]);
                    mma_bf16(acc[mt][nt4 * 2 + 1], afr[cur][mt], bfr[cur][nt4][1], bfr[cur][nt4][3]);
                }
            }
        }
    }

    // ---------------- epilogue: branch-free partial LSE (target included) ----------------
    float* rsum = (float*)(SA + SM_RSUM);
    int g = lid >> 2;
    int tg = lid & 3;

    float rs[4] = {0.f, 0.f, 0.f, 0.f};
    #pragma unroll
    for (int mt = 0; mt < 2; mt++) {
        int rlo = warpM * 32 + mt * 16 + g;
        int rhi = rlo + 8;
        int tlo = tgt_s[rlo];
        int thi = tgt_s[rhi];
        #pragma unroll
        for (int nt = 0; nt < 8; nt++) {
            int colb = warpN * 64 + nt * 8 + tg * 2;
            #pragma unroll
            for (int q = 0; q < 4; q++) {
                int cls = cls0 + colb + (q & 1);
                float cosv = acc[mt][nt][q];
                int t = (q < 2) ? tlo : thi;
                if (cls == t) g_cost[b0 + ((q < 2) ? rlo : rhi)] = cosv;
                rs[mt * 2 + (q >> 1)] += ex2_approx(fmaf(EXPK, cosv, -EXPK));
            }
        }
    }
    #pragma unroll
    for (int i = 0; i < 4; i++) {
        rs[i] += __shfl_xor_sync(0xffffffffu, rs[i], 1);
        rs[i] += __shfl_xor_sync(0xffffffffu, rs[i], 2);
    }
    if (tg == 0) {
        #pragma unroll
        for (int mt = 0; mt < 2; mt++) {
            int rlo = warpM * 32 + mt * 16 + g;
            rsum[rlo * 2 + warpN] = rs[mt * 2 + 0];
            rsum[(rlo + 8) * 2 + warpN] = rs[mt * 2 + 1];
        }
    }
    __syncthreads();
    if (tid < 128) {
        g_partials[(size_t)(b0 + tid) * PPAD + ctile] = rsum[tid * 2] + rsum[tid * 2 + 1];
    }
}

// ======================= K3: reduce + margin + final mean (fused) =======================
__global__ void __launch_bounds__(256) k_reduce_b(float* __restrict__ out) {
    __shared__ unsigned last;
    int tid = threadIdx.x;
    int wid = tid >> 5;
    int lane = tid & 31;
    int b = blockIdx.x * 8 + wid;

    float acc = 0.0f;
    for (int i = lane; i < NCTA; i += 32)
        acc += g_partials[(size_t)b * PPAD + i];
    #pragma unroll
    for (int m = 16; m >= 1; m >>= 1) acc += __shfl_xor_sync(0xffffffffu, acc, m);
    if (lane == 0) {
        float ct = g_cost[b];
        acc -= ex2_approx(fmaf(EXPK, ct, -EXPK));   // bit-identical to gemm's added term
        float st = sqrtf(fmaxf(1.0f - ct * ct, 0.0f));
        float phi = ct * C_COS_M - st * C_SIN_M;
        phi = (ct > C_TH) ? phi : (ct - C_MM);
        acc += ex2_approx(fmaf(EXPK, phi, -EXPK));
        g_lossb[b] = 64.0f + logf(acc) - 64.0f * phi;
    }
    __threadfence();
    __syncthreads();
    if (tid == 0) last = atomicAdd(&g_ctr, 1u);
    __syncthreads();
    if (last == 63u) {
        __shared__ float red[8];
        float v = g_lossb[tid] + g_lossb[tid + 256];
        #pragma unroll
        for (int m = 16; m >= 1; m >>= 1) v += __shfl_xor_sync(0xffffffffu, v, m);
        if (lane == 0) red[wid] = v;
        __syncthreads();
        if (tid == 0) {
            float s = 0.0f;
            #pragma unroll
            for (int i = 0; i < 8; i++) s += red[i];
            out[0] = s * (1.0f / (float)BATCHN);
        }
    }
}

// ======================= launch: 2-stream overlapped pipeline =======================
static cudaStream_t g_s2 = nullptr;
static cudaEvent_t g_evN[NSLICE];     // norm slice i done (recorded on main)
static cudaEvent_t g_evJ = nullptr;   // join (recorded on s2)
static bool g_init = false, g_ok = false;

static void lazy_init() {
    if (g_init) return;
    g_init = true;
    if (cudaStreamCreateWithFlags(&g_s2, cudaStreamNonBlocking) != cudaSuccess) return;
    for (int i = 0; i < NSLICE; i++)
        if (cudaEventCreateWithFlags(&g_evN[i], cudaEventDisableTiming) != cudaSuccess) return;
    if (cudaEventCreateWithFlags(&g_evJ, cudaEventDisableTiming) != cudaSuccess) return;
    g_ok = true;
}

extern "C" void kernel_launch(void* const* d_in, const int* in_sizes, int n_in,
                              void* d_out, int out_size) {
    const float* x = (const float*)d_in[0];
    const float* w = (const float*)d_in[1];
    const int* tgt_raw = (const int*)d_in[2];
    float* out = (float*)d_out;

    cudaFuncSetAttribute(k_gemm, cudaFuncAttributeMaxDynamicSharedMemorySize, SMEM_DYN);
    lazy_init();

    if (g_ok) {
        // main stream (0): x-norm + weight-norm slices, event after each
        k_norm_x<<<BATCHN, 128>>>(x, tgt_raw);
        for (int i = 0; i < NSLICE; i++) {
            int row0 = SLICE_OFF[i] * 128;
            int nrows = (SLICE_OFF[i + 1] - SLICE_OFF[i]) * 128;
            k_norm_w<<<nrows / 4, 128>>>(w, row0);
            cudaEventRecord(g_evN[i], 0);
        }
        // side stream: gemm slice i waits norm slice i
        for (int i = 0; i < NSLICE; i++) {
            cudaStreamWaitEvent(g_s2, g_evN[i], 0);
            int nct = SLICE_OFF[i + 1] - SLICE_OFF[i];
            k_gemm<<<nct * 4, 256, SMEM_DYN, g_s2>>>(SLICE_OFF[i]);
        }
        k_reduce_b<<<64, 256, 0, g_s2>>>(out);
        cudaEventRecord(g_evJ, g_s2);
        cudaStreamWaitEvent(0, g_evJ, 0);      // join back to main stream
    } else {
        // sequential fallback
        k_norm_x<<<BATCHN, 128>>>(x, tgt_raw);
        k_norm_w<<<CPAD / 4, 128>>>(w, 0);
        k_gemm<<<NCTA * 4, 256, SMEM_DYN>>>(0);
        k_reduce_b<<<64, 256>>>(out);
    }
}